// round 14
// baseline (speedup 1.0000x reference)
#include <cuda_runtime.h>
#include <math.h>

// Problem constants
#define NXg 302
#define NYg 394
#define Bb  16
#define Dd  128
#define KK  16
#define UNITS 96
#define NP   197                // column pairs per row
#define SPR  25                 // 16-pt strips per row (last has 5 pairs)
#define WPBATCH (NXg * SPR)     // 7550 strips per batch
#define TPB 256
#define RPBLK (TPB / 4)         // 64 strips per block-chunk (4 threads/strip)
#define NCHUNK 2
#define BPB 59                  // 59*2*64 = 7552 >= 7550

typedef unsigned long long u64;

// ---------------------------------------------------------------------------
// f32x2 packed helpers
// ---------------------------------------------------------------------------
__device__ __forceinline__ u64 pack2f(float lo, float hi) {
    u64 d; asm("mov.b64 %0, {%1, %2};" : "=l"(d) : "f"(lo), "f"(hi)); return d;
}
__device__ __forceinline__ void unpack2f(u64 s, float& lo, float& hi) {
    asm("mov.b64 {%0, %1}, %2;" : "=f"(lo), "=f"(hi) : "l"(s));
}
__device__ __forceinline__ u64 f2fma(u64 a, u64 b, u64 c) {
    u64 d; asm("fma.rn.f32x2 %0, %1, %2, %3;" : "=l"(d) : "l"(a), "l"(b), "l"(c)); return d;
}
__device__ __forceinline__ u64 f2add(u64 a, u64 b) {
    u64 d; asm("add.rn.f32x2 %0, %1, %2;" : "=l"(d) : "l"(a), "l"(b)); return d;
}
__device__ __forceinline__ u64 f2mul(u64 a, u64 b) {
    u64 d; asm("mul.rn.f32x2 %0, %1, %2;" : "=l"(d) : "l"(a), "l"(b)); return d;
}
__device__ __forceinline__ float ex2a(float x) {
    float y; asm("ex2.approx.f32 %0, %1;" : "=f"(y) : "f"(x)); return y;
}
__device__ __forceinline__ float lg2a(float x) {
    float y; asm("lg2.approx.f32 %0, %1;" : "=f"(y) : "f"(x)); return y;
}

// packed exp2 via MUFU; very negative args flush to +0 (correct for anchor)
__device__ __forceinline__ u64 exp2E(u64 ap)
{
    float a0, a1; unpack2f(ap, a0, a1);
    return pack2f(ex2a(a0), ex2a(a1));
}

// packed exp2 via MUFU, arg clamped above at +6 (prevents 0*inf in dead zones)
__device__ __forceinline__ u64 exp2R(u64 ap)
{
    float a0, a1; unpack2f(ap, a0, a1);
    return pack2f(ex2a(fminf(a0, 6.0f)), ex2a(fminf(a1, 6.0f)));
}

// ---------------------------------------------------------------------------
// Fused kernel: 16-pt strips, 4-way k split, 2 sequential chunks per thread.
// Prologue: vectorized redundant GEMM (float4) + MUFU-approx softmax/params.
// Main: each thread runs anchor + 7-step recurrence for its 4 components;
// reduce-scatter combine leaves each thread owning the 2 pairs it stores.
// ---------------------------------------------------------------------------
__global__ __launch_bounds__(TPB) void mdn_fused_kernel(
    const float* __restrict__ inp,
    const float* __restrict__ w,
    const float* __restrict__ bias,
    float* __restrict__ out)
{
    __shared__ float s_in[Dd];
    __shared__ float s_part[8][UNITS];
    __shared__ float s_y[UNITS];
    __shared__ u64 sp[KK * 10];   // packed-dup params

    const int b = blockIdx.y;
    const int t = threadIdx.x;

    if (t < Dd) s_in[t] = inp[b * Dd + t];
    __syncthreads();

    // vectorized split GEMM: 192 threads; g = t%24 (units 4g..4g+3),
    // c = t/24 (depth 16c..16c+15); 16 LDG.128 + 64 FMA each
    if (t < 192) {
        const int g = t % 24;
        const int c = t / 24;
        const float* wc = w + (c * 16) * UNITS + 4 * g;
        const float* ic = s_in + c * 16;
        float4 acc = make_float4(0.f, 0.f, 0.f, 0.f);
#pragma unroll
        for (int dd = 0; dd < 16; ++dd) {
            const float4 wv = *reinterpret_cast<const float4*>(wc + dd * UNITS);
            const float xi = ic[dd];
            acc.x = fmaf(xi, wv.x, acc.x);
            acc.y = fmaf(xi, wv.y, acc.y);
            acc.z = fmaf(xi, wv.z, acc.z);
            acc.w = fmaf(xi, wv.w, acc.w);
        }
        *reinterpret_cast<float4*>(&s_part[c][4 * g]) = acc;
    }
    __syncthreads();

    if (t < UNITS) {
        float y = bias[t];
#pragma unroll
        for (int c = 0; c < 8; ++c) y += s_part[c][t];
        s_y[t] = y;
    }
    __syncthreads();

    if (t < KK) {
        const int k = t;
        const float LOG2E    = 1.4426950408889634f;
        const float LOG2_2PI = 2.6514961294723187f;
        const float K2E      = -0.7213475204444817f;   // -0.5*log2(e)

        const float mux = s_y[2 * k];
        const float muy = s_y[2 * k + 1];
        const float aa  = s_y[2 * KK + 3 * k];
        const float s22 = s_y[2 * KK + 3 * k + 1];
        const float s11 = s_y[2 * KK + 3 * k + 2];
        const float pik = s_y[5 * KK + k];

        // shuffle softmax stats across lanes 0..15 (MUFU approx exp)
        float m = pik;
#pragma unroll
        for (int s = 1; s < KK; s <<= 1)
            m = fmaxf(m, __shfl_xor_sync(0x0000FFFFu, m, s));
        float S = ex2a((pik - m) * LOG2E);
#pragma unroll
        for (int s = 1; s < KK; s <<= 1)
            S += __shfl_xor_sync(0x0000FFFFu, S, s);

        const float A1 = ex2a(-s11 * LOG2E);   // 1/L11
        const float A2 = ex2a(-s22 * LOG2E);   // 1/L22
        const float LC = (pik - m - s11 - s22) * LOG2E - lg2a(S) - LOG2_2PI;

        const float dyv = 1.0f / (NYg - 1);
        const float Sstep = 2.0f * A2 * dyv;           // z2 step for dj=2
        const float G1 = 2.0f * K2E * Sstep;
        const float G0 = K2E * Sstep * Sstep;
        const float c  = ex2a(G1 * Sstep);             // ratio of ratios

        u64* P = &sp[k * 10];
        P[0] = pack2f(A1, A1);
        P[1] = pack2f(-mux * A1, -mux * A1);
        P[2] = pack2f(A2, A2);
        P[3] = pack2f(-muy * A2, -muy * A2);
        P[4] = pack2f(-aa * A2, -aa * A2);
        P[5] = pack2f(LC, LC);
        P[6] = pack2f(G1, G1);
        P[7] = pack2f(G0, G0);
        P[8] = pack2f(c, c);
        P[9] = 0ULL;
    }
    __syncthreads();

    // ---- main eval: 2 sequential strip-chunks per thread ----
    const int kq   = t & 3;                  // k quarter
    const int lrun = t >> 2;                 // strip-within-chunk
    const u64 K2EP = 0xBF38AA3BBF38AA3BULL;  // {-0.72134752f, -0.72134752f}
    const float dy = 1.0f / (NYg - 1);
    const int kbase = kq * (KK / 4);

#pragma unroll 1
    for (int ch = 0; ch < NCHUNK; ++ch) {
        const int wi0 = (blockIdx.x + ch * BPB) * RPBLK + lrun;
        const bool valid = (wi0 < WPBATCH);
        const int wi = valid ? wi0 : (WPBATCH - 1);

        const int i     = wi / SPR;
        const int strip = wi - i * SPR;
        const int j0    = strip * 16;

        const float x  = (float)i * (1.0f / (NXg - 1));
        const float y0 = (float)j0 * dy;
        const float y1 = (float)(j0 + 1) * dy;

        const u64 xp = pack2f(x, x);
        const u64 yp = pack2f(y0, y1);

        u64 acc[8];
#pragma unroll
        for (int n = 0; n < 8; ++n) acc[n] = 0ULL;

#pragma unroll
        for (int kk = 0; kk < KK / 4; ++kk) {
            const int k = kbase + kk;
            const ulonglong2 q0 = *reinterpret_cast<const ulonglong2*>(&sp[k * 10 + 0]); // A1,B1
            const ulonglong2 q1 = *reinterpret_cast<const ulonglong2*>(&sp[k * 10 + 2]); // A2,B2
            const ulonglong2 q2 = *reinterpret_cast<const ulonglong2*>(&sp[k * 10 + 4]); // C2,LC
            const ulonglong2 q3 = *reinterpret_cast<const ulonglong2*>(&sp[k * 10 + 6]); // G1,G0
            const u64 cP = sp[k * 10 + 8];

            u64 z1  = f2fma(xp, q0.x, q0.y);
            u64 z1s = f2mul(z1, z1);
            u64 W   = f2fma(q2.x, z1, q1.y);
            u64 z2  = f2fma(yp, q1.x, W);
            u64 m   = f2fma(z2, z2, z1s);
            u64 a0  = f2fma(m, K2EP, q2.y);
            u64 E   = exp2E(a0);
            u64 dq  = f2fma(z2, q3.x, q3.y);
            u64 r   = exp2R(dq);

            acc[0] = f2add(acc[0], E);
#pragma unroll
            for (int n = 1; n < 8; ++n) {
                E = f2mul(E, r);
                if (n < 7) r = f2mul(r, cP);
                acc[n] = f2add(acc[n], E);
            }
        }

        // reduce-scatter across 4 k-quarter threads (lanes 4s..4s+3):
        // round 1 (xor 2) keeps 4 accs; round 2 (xor 1) keeps 2.
        u64 accL[4];
#pragma unroll
        for (int n = 0; n < 4; ++n) {
            const u64 pl = __shfl_xor_sync(0xFFFFFFFFu, acc[n], 2);
            const u64 ph = __shfl_xor_sync(0xFFFFFFFFu, acc[n + 4], 2);
            accL[n] = (t & 2) ? f2add(acc[n + 4], ph) : f2add(acc[n], pl);
        }
        u64 accF[2];
#pragma unroll
        for (int n = 0; n < 2; ++n) {
            const u64 pl = __shfl_xor_sync(0xFFFFFFFFu, accL[n], 1);
            const u64 ph = __shfl_xor_sync(0xFFFFFFFFu, accL[n + 2], 1);
            accF[n] = (t & 1) ? f2add(accL[n + 2], ph) : f2add(accL[n], pl);
        }

        if (valid) {
            u64* o64 = reinterpret_cast<u64*>(out);
            const size_t base = (size_t)(b * NXg + i) * NP + strip * 8;
            const int npairs = min(8, NP - strip * 8);   // 8 normally, 5 on tail
#pragma unroll
            for (int n = 0; n < 2; ++n) {
                const int p = 2 * kq + n;
                if (p < npairs) o64[base + p] = accF[n];
            }
        }
    }
}

// ---------------------------------------------------------------------------
extern "C" void kernel_launch(void* const* d_in, const int* in_sizes, int n_in,
                              void* d_out, int out_size)
{
    const float* inp  = (const float*)d_in[0];   // [16,128]
    const float* w    = (const float*)d_in[1];   // [128,96]
    const float* bias = (const float*)d_in[2];   // [96]
    float* out = (float*)d_out;                  // [16,302,394,1]

    dim3 grid(BPB, Bb);
    mdn_fused_kernel<<<grid, TPB>>>(inp, w, bias, out);
}

// round 15
// speedup vs baseline: 1.3133x; 1.3133x over previous
#include <cuda_runtime.h>
#include <math.h>

// Problem constants
#define NXg 302
#define NYg 394
#define Bb  16
#define Dd  128
#define KK  16
#define UNITS 96
#define NP   197                // float2 column pairs per row
#define SPR  25                 // 16-pt strips per row (last strip = 10 pts)
#define WPBATCH (NXg * SPR)     // 7550 strips per batch
#define TPB 256
#define BPB ((WPBATCH + TPB - 1) / TPB)   // 30 blocks per batch

__device__ __forceinline__ float ex2a(float x) {
    float y; asm("ex2.approx.f32 %0, %1;" : "=f"(y) : "f"(x)); return y;
}

// ---------------------------------------------------------------------------
// Fused kernel, fully scalar eval.
// Prologue: vectorized redundant GEMM (float4) + shuffle softmax + scalar
// per-component constants (NOT duplicated).
// Main: one thread = one 16-point strip x all 16 components. Per k: scalar
// setup + MUFU anchor + stride-1 geometric recurrence (3 scalar ops/point).
// No shuffles, no 64-bit packing -- ptxas gets clean scalar code.
// ---------------------------------------------------------------------------
__global__ __launch_bounds__(TPB) void mdn_fused_kernel(
    const float* __restrict__ inp,
    const float* __restrict__ w,
    const float* __restrict__ bias,
    float* __restrict__ out)
{
    __shared__ float s_in[Dd];
    __shared__ float s_part[8][UNITS];
    __shared__ float s_y[UNITS];
    __shared__ float sp[KK * 12];   // scalar params, stride 12 (16B aligned)

    const int b = blockIdx.y;
    const int t = threadIdx.x;

    if (t < Dd) s_in[t] = inp[b * Dd + t];
    __syncthreads();

    // vectorized split GEMM: 192 threads; g = t%24 (units 4g..4g+3),
    // c = t/24 (depth 16c..16c+15); 16 LDG.128 + 64 FMA each
    if (t < 192) {
        const int g = t % 24;
        const int c = t / 24;
        const float* wc = w + (c * 16) * UNITS + 4 * g;
        const float* ic = s_in + c * 16;
        float4 acc = make_float4(0.f, 0.f, 0.f, 0.f);
#pragma unroll
        for (int dd = 0; dd < 16; ++dd) {
            const float4 wv = *reinterpret_cast<const float4*>(wc + dd * UNITS);
            const float xi = ic[dd];
            acc.x = fmaf(xi, wv.x, acc.x);
            acc.y = fmaf(xi, wv.y, acc.y);
            acc.z = fmaf(xi, wv.z, acc.z);
            acc.w = fmaf(xi, wv.w, acc.w);
        }
        *reinterpret_cast<float4*>(&s_part[c][4 * g]) = acc;
    }
    __syncthreads();

    if (t < UNITS) {
        float y = bias[t];
#pragma unroll
        for (int c = 0; c < 8; ++c) y += s_part[c][t];
        s_y[t] = y;
    }
    __syncthreads();

    if (t < KK) {
        const int k = t;
        const float LOG2E    = 1.4426950408889634f;
        const float LOG2_2PI = 2.6514961294723187f;
        const float K2E      = -0.7213475204444817f;   // -0.5*log2(e)

        const float mux = s_y[2 * k];
        const float muy = s_y[2 * k + 1];
        const float aa  = s_y[2 * KK + 3 * k];
        const float s22 = s_y[2 * KK + 3 * k + 1];
        const float s11 = s_y[2 * KK + 3 * k + 2];
        const float pik = s_y[5 * KK + k];

        // shuffle softmax stats across lanes 0..15
        float m = pik;
#pragma unroll
        for (int s = 1; s < KK; s <<= 1)
            m = fmaxf(m, __shfl_xor_sync(0x0000FFFFu, m, s));
        float S = ex2a((pik - m) * LOG2E);
#pragma unroll
        for (int s = 1; s < KK; s <<= 1)
            S += __shfl_xor_sync(0x0000FFFFu, S, s);
        float lg2S; asm("lg2.approx.f32 %0, %1;" : "=f"(lg2S) : "f"(S));

        const float A1 = ex2a(-s11 * LOG2E);   // 1/L11
        const float A2 = ex2a(-s22 * LOG2E);   // 1/L22
        const float LC = (pik - m - s11 - s22) * LOG2E - lg2S - LOG2_2PI;

        const float dyv = 1.0f / (NYg - 1);
        const float S1 = A2 * dyv;             // z2 step per +1 column
        const float G1 = 2.0f * K2E * S1;
        const float G0 = K2E * S1 * S1;
        const float cs = ex2a(G1 * S1);        // ratio of ratios (<1)

        float* P = &sp[k * 12];
        P[0] = A1;
        P[1] = -mux * A1;
        P[2] = A2;
        P[3] = -muy * A2;
        P[4] = -aa * A2;
        P[5] = LC;
        P[6] = G1;
        P[7] = G0;
        P[8] = cs;
        P[9] = 0.0f; P[10] = 0.0f; P[11] = 0.0f;
    }
    __syncthreads();

    // ---- main eval (scalar) ----
    const int wi = blockIdx.x * TPB + t;
    if (wi >= WPBATCH) return;     // safe: no syncs/shuffles below

    const int i     = wi / SPR;
    const int strip = wi - i * SPR;
    const int j0    = strip * 16;

    const float x  = (float)i * (1.0f / (NXg - 1));
    const float y0 = (float)j0 * (1.0f / (NYg - 1));
    const float K2E = -0.7213475204444817f;

    float acc[16];
#pragma unroll
    for (int n = 0; n < 16; ++n) acc[n] = 0.0f;

#pragma unroll
    for (int k = 0; k < KK; ++k) {
        const float4 pa = *reinterpret_cast<const float4*>(&sp[k * 12]);     // A1,B1,A2,B2
        const float4 pb = *reinterpret_cast<const float4*>(&sp[k * 12 + 4]); // C2,LC,G1,G0
        const float cs  = sp[k * 12 + 8];

        const float z1  = fmaf(x, pa.x, pa.y);
        const float z1s = z1 * z1;
        const float W   = fmaf(pb.x, z1, pa.w);
        const float z2  = fmaf(y0, pa.z, W);
        const float m   = fmaf(z2, z2, z1s);
        const float a0  = fmaf(m, K2E, pb.y);
        float E = ex2a(a0);                          // flushes to +0 far away
        const float dq = fmaf(z2, pb.z, pb.w);
        float r = ex2a(fminf(dq, 12.0f));            // cheap insurance clamp

        acc[0] += E;
#pragma unroll
        for (int n = 1; n < 16; ++n) {
            E *= r;
            if (n < 15) r *= cs;
            acc[n] += E;
        }
    }

    // store 8 float2 pairs (5 on the tail strip: 394 = 24*16 + 10)
    float2* o2 = reinterpret_cast<float2*>(out);
    const size_t base = (size_t)(b * NXg + i) * NP + strip * 8;
    const int npairs = min(8, NP - strip * 8);
#pragma unroll
    for (int n = 0; n < 8; ++n)
        if (n < npairs) o2[base + n] = make_float2(acc[2 * n], acc[2 * n + 1]);
}

// ---------------------------------------------------------------------------
extern "C" void kernel_launch(void* const* d_in, const int* in_sizes, int n_in,
                              void* d_out, int out_size)
{
    const float* inp  = (const float*)d_in[0];   // [16,128]
    const float* w    = (const float*)d_in[1];   // [128,96]
    const float* bias = (const float*)d_in[2];   // [96]
    float* out = (float*)d_out;                  // [16,302,394,1]

    dim3 grid(BPB, Bb);
    mdn_fused_kernel<<<grid, TPB>>>(inp, w, bias, out);
}